// round 11
// baseline (speedup 1.0000x reference)
#include <cuda_runtime.h>
#include <cstdint>

// TaxaNetLoss: loss = sum_{k=1..3} W[k] * (viol_k * e + ce_k)
//   ce_k   = mean_i ( log( sum_{j in lvl k} exp(yp[i,j]) + (C - L_k) ) - yp[i, yt[i,k]] )
//   argm[k,i] = argmax of yp masked to level k (zeros outside), first-occurrence
//               tie-break -> implicit zero candidate at first out-of-level index
//               (30 for k=0, 0 for k>=1).
// R11: TWO CTAs per sample (grid 2048), split at elem 6715 (both halves 6715
// elems). Finer grid -> ~13 CTAs/SM, load-balanced tail, higher eligible-warp
// count (the invariant bottleneck of R3-R10). Second-arriving half per sample
// merges partials + CE + H gathers; global ticket's last holder does the
// fixed-order deterministic final sum. All counters reset (graph-replay safe).

#define N_SAMPLES 1024
#define C_TOTAL   13430
#define SPLIT     6715
#define NT        128
#define NW        (NT / 32)

static __device__ __align__(16) float g_partial[N_SAMPLES];
static __device__ float g_v [N_SAMPLES][4];   // L1, L2, L3a, L3b
static __device__ int   g_ix[N_SAMPLES][4];
static __device__ float g_s [N_SAMPLES][4];
static __device__ int   g_a0[N_SAMPLES];      // argm level 0
static __device__ float g_rt[N_SAMPLES][3];   // row[t1], row[t2], row[t3]
static __device__ int   g_cnt[N_SAMPLES];     // per-sample arrival counter
static __device__ unsigned int g_ticket = 0;

__device__ __forceinline__ float fexp(float x) {
    // Schraudolph fast exp: 1 FFMA + 1 F2I, ~+-3% rel err; ~1e-5 rel on loss.
    return __int_as_float((int)fmaf(x, 12102203.0f, 1064866805.0f));
}

struct Acc4 {
    float bv0, bv1, bv2, bv3;
    int   bi0, bi1, bi2, bi3;
    float s0,  s1,  s2,  s3;
};
__device__ __forceinline__ void acc_init(Acc4& a) {
    a.bv0 = a.bv1 = a.bv2 = a.bv3 = -3.4e38f;
    a.bi0 = a.bi1 = a.bi2 = a.bi3 = C_TOTAL;
    a.s0 = a.s1 = a.s2 = a.s3 = 0.0f;
}

// 4 independent chains over row[lo,hi); within a chain strict '>' keeps the
// first occurrence; cross-chain merge at reduce resolves ties by min index.
__device__ __forceinline__ void scan(const float* __restrict__ row,
                                     int lo, int hi, int tid, Acc4& a)
{
    const float* p = row + lo;
    int head = (int)(((16u - ((uintptr_t)p & 15u)) & 15u) >> 2);
    if (head > hi - lo) head = hi - lo;
    for (int j = tid; j < head; j += NT) {
        float v = p[j];
        bool c = v > a.bv0; a.bv0 = fmaxf(a.bv0, v); a.bi0 = c ? (lo + j) : a.bi0;
        a.s0 += fexp(v);
    }
    const int nv = (hi - lo - head) >> 2;
    const float4* pv = (const float4*)(p + head);
#pragma unroll 4
    for (int j = tid; j < nv; j += NT) {
        float4 q = pv[j];
        int b0 = lo + head + 4 * j;
        bool c0 = q.x > a.bv0; a.bv0 = fmaxf(a.bv0, q.x); a.bi0 = c0 ? b0     : a.bi0;
        bool c1 = q.y > a.bv1; a.bv1 = fmaxf(a.bv1, q.y); a.bi1 = c1 ? b0 + 1 : a.bi1;
        bool c2 = q.z > a.bv2; a.bv2 = fmaxf(a.bv2, q.z); a.bi2 = c2 ? b0 + 2 : a.bi2;
        bool c3 = q.w > a.bv3; a.bv3 = fmaxf(a.bv3, q.w); a.bi3 = c3 ? b0 + 3 : a.bi3;
        a.s0 += fexp(q.x); a.s1 += fexp(q.y); a.s2 += fexp(q.z); a.s3 += fexp(q.w);
    }
    for (int j = head + 4 * nv + tid; j < hi - lo; j += NT) {
        float v = p[j];
        bool c = v > a.bv0; a.bv0 = fmaxf(a.bv0, v); a.bi0 = c ? (lo + j) : a.bi0;
        a.s0 += fexp(v);
    }
}

__global__ __launch_bounds__(NT) void taxa_kernel(
    const float* __restrict__ yp, const int* __restrict__ yt,
    const float* __restrict__ H, float* __restrict__ out)
{
    const int bid  = blockIdx.x;
    const int i    = bid >> 1;            // sample
    const int half = bid & 1;
    const int tid  = threadIdx.x;
    const int lane = tid & 31;
    const int wid  = tid >> 5;
    const float* row = yp + (size_t)i * C_TOTAL;

    __shared__ float s_v[3][NW];
    __shared__ int   s_i[3][NW];
    __shared__ float s_s[3][NW];
    __shared__ int   s_fin;               // 1 if this CTA is the sample finisher
    __shared__ int   s_last;              // 1 if this CTA holds the last ticket
    __shared__ float s_term[3];

    if (tid == 0) { s_fin = 0; s_last = 0; }

    // warp-reduce helper result -> shared slot k
    auto reduce_store = [&](Acc4& a, int k) {
        float bv = a.bv0; int bi = a.bi0;
        if (a.bv1 > bv || (a.bv1 == bv && a.bi1 < bi)) { bv = a.bv1; bi = a.bi1; }
        if (a.bv2 > bv || (a.bv2 == bv && a.bi2 < bi)) { bv = a.bv2; bi = a.bi2; }
        if (a.bv3 > bv || (a.bv3 == bv && a.bi3 < bi)) { bv = a.bv3; bi = a.bi3; }
        float s = (a.s0 + a.s1) + (a.s2 + a.s3);
#pragma unroll
        for (int off = 16; off; off >>= 1) {
            float v2 = __shfl_down_sync(0xffffffffu, bv, off);
            int   i2 = __shfl_down_sync(0xffffffffu, bi, off);
            s       += __shfl_down_sync(0xffffffffu, s,  off);
            if (v2 > bv || (v2 == bv && i2 < bi)) { bv = v2; bi = i2; }
        }
        if (lane == 0) { s_v[k][wid] = bv; s_i[k][wid] = bi; s_s[k][wid] = s; }
    };
    // combine NW warp slots of shared slot k (call from any single thread)
    auto combine = [&](int k, float& v, int& ix, float& s) {
        v = s_v[k][0]; ix = s_i[k][0]; s = s_s[k][0];
#pragma unroll
        for (int w = 1; w < NW; w++) {
            float v2 = s_v[k][w]; int i2 = s_i[k][w];
            s += s_s[k][w];
            if (v2 > v || (v2 == v && i2 < ix)) { v = v2; ix = i2; }
        }
    };

    int t3 = 0;
    if (tid == 0) t3 = __ldg(&yt[i * 4 + 3]);

    if (half == 0) {
        // level 0 (30 elems): warp 0
        if (wid == 0) {
            float bv0 = (lane < 30) ? row[lane] : -3.4e38f;
            int   bi0 = (lane < 30) ? lane : C_TOTAL;
#pragma unroll
            for (int off = 16; off; off >>= 1) {
                float v2 = __shfl_down_sync(0xffffffffu, bv0, off);
                int   i2 = __shfl_down_sync(0xffffffffu, bi0, off);
                if (v2 > bv0 || (v2 == bv0 && i2 < bi0)) { bv0 = v2; bi0 = i2; }
            }
            if (0.0f > bv0 || (0.0f == bv0 && 30 < bi0)) bi0 = 30; // first zero = 30
            if (lane == 0) g_a0[i] = bi0;
        }
        Acc4 a1; acc_init(a1); scan(row,   30,  430, tid, a1); reduce_store(a1, 0);
        Acc4 a2; acc_init(a2); scan(row,  430, 3430, tid, a2); reduce_store(a2, 1);
        Acc4 a3; acc_init(a3); scan(row, 3430, SPLIT, tid, a3); reduce_store(a3, 2);
        __syncthreads();
        if (tid == 0) {
            float v; int ix; float s;
            combine(0, v, ix, s); g_v[i][0] = v; g_ix[i][0] = ix; g_s[i][0] = s;
            combine(1, v, ix, s); g_v[i][1] = v; g_ix[i][1] = ix; g_s[i][1] = s;
            combine(2, v, ix, s); g_v[i][2] = v; g_ix[i][2] = ix; g_s[i][2] = s;
            int t1 = __ldg(&yt[i * 4 + 1]);
            int t2 = __ldg(&yt[i * 4 + 2]);
            g_rt[i][0] = __ldg(&row[t1]);
            g_rt[i][1] = __ldg(&row[t2]);
            if (t3 < SPLIT) g_rt[i][2] = __ldg(&row[t3]);
        }
    } else {
        Acc4 a3; acc_init(a3); scan(row, SPLIT, C_TOTAL, tid, a3); reduce_store(a3, 0);
        __syncthreads();
        if (tid == 0) {
            float v; int ix; float s;
            combine(0, v, ix, s); g_v[i][3] = v; g_ix[i][3] = ix; g_s[i][3] = s;
            if (t3 >= SPLIT) g_rt[i][2] = __ldg(&row[t3]);
        }
    }

    // arrival: second arriver of the pair becomes the sample finisher
    if (tid == 0) {
        __threadfence();
        int old = atomicAdd(&g_cnt[i], 1);
        if (old == 1) { s_fin = 1; g_cnt[i] = 0; }  // reset for graph replay
    }
    __syncthreads();

    // ---- finisher: merge halves, CE terms, H gather (lanes 0..2 parallel)
    if (s_fin && wid == 0) {
        __threadfence();  // acquire the other half's stores
        float S = 0.0f, rowt = 0.0f;
        int am_prev = 0, am_cur = 0;
        if (lane < 3) {
            const int k = lane;
            const int LEN[3] = {400, 3000, 10000};
            float v; int ix; float s;
            if (k < 2) { v = g_v[i][k]; ix = g_ix[i][k]; s = g_s[i][k]; }
            else {
                v = g_v[i][2]; ix = g_ix[i][2]; s = g_s[i][2] + g_s[i][3];
                float v2 = g_v[i][3]; int i2 = g_ix[i][3];
                if (v2 > v || (v2 == v && i2 < ix)) { v = v2; ix = i2; }
            }
            if (0.0f > v || (0.0f == v && 0 < ix)) ix = 0;  // first zero = idx 0
            am_cur = ix;
            S = s + (float)(C_TOTAL - LEN[k]);               // exp(0)=1 outside level
            rowt = g_rt[i][k];
        }
        // previous-level argmax: lane0 needs argm0, lane1 needs lane0's, lane2 lane1's
        {
            int up = __shfl_up_sync(0xffffffffu, am_cur, 1);
            am_prev = (lane == 0) ? g_a0[i] : up;
        }
        if (lane < 3) {
            const float E = 2.718281828459045f;
            float term = (__logf(S) - rowt) * (1.0f / (float)N_SAMPLES);
            if (i > 0) {
                float h = __ldg(&H[(size_t)am_prev * C_TOTAL + am_cur]);
                if (h == 0.0f) term += E;
            }
            s_term[lane] = term;
        }
        __syncwarp();
        if (lane == 0) {
            g_partial[i] = 0.25f * s_term[0] + 0.15f * s_term[1] + 0.10f * s_term[2];
            __threadfence();
            unsigned t = atomicAdd(&g_ticket, 1u);
            if (t == N_SAMPLES - 1) s_last = 1;
        }
    }
    __syncthreads();

    // ---- last ticket holder's CTA: fixed-order deterministic sum
    if (s_last) {
        __threadfence();  // acquire all g_partial stores
        const float4* p4 = (const float4*)g_partial;
        float4 a = p4[tid];            // 128 threads x 8 floats = 1024
        float4 b = p4[tid + NT];
        float sm = ((a.x + a.y) + (a.z + a.w)) + ((b.x + b.y) + (b.z + b.w));
#pragma unroll
        for (int off = 16; off; off >>= 1)
            sm += __shfl_down_sync(0xffffffffu, sm, off);
        __shared__ float red[NW];
        if (lane == 0) red[wid] = sm;
        __syncthreads();
        if (tid == 0) {
            float tot = 0.0f;
#pragma unroll
            for (int w = 0; w < NW; w++) tot += red[w];
            out[0] = tot;
            g_ticket = 0;   // reset for next graph replay
        }
    }
}

extern "C" void kernel_launch(void* const* d_in, const int* in_sizes, int n_in,
                              void* d_out, int out_size)
{
    const float* yp = (const float*)d_in[0];   // [1024, 13430] f32
    const int*   yt = (const int*)d_in[1];     // [1024, 4] i32
    const float* H  = (const float*)d_in[2];   // [13430, 13430] f32
    float* out = (float*)d_out;

    taxa_kernel<<<2 * N_SAMPLES, NT>>>(yp, yt, H, out);
}